// round 2
// baseline (speedup 1.0000x reference)
#include <cuda_runtime.h>
#include <cuda_bf16.h>
#include <cstdint>

// Problem constants (fixed by the reference setup)
#define N_NODES   128
#define M_PAR     2
#define CAL_N     256
#define N_OBS     64
#define SPB       128    // samples per block in main kernel

// Device scratch (allocation-free rule: __device__ globals)
__device__ float  g_pilot[N_NODES * CAL_N];
__device__ float4 g_cA[N_NODES];   // {w0, w1, b, scale}   (root: {0,0,0,1})
__device__ int    g_cP[N_NODES];   // p0 | p1<<8 | root<<16

// ---------------------------------------------------------------------------
// K1: pilot pass. 1 block, 256 threads (one per calibration sample).
// x_i = relu(w.x_par + b) for non-root, x_i = root_pilot[i] for root. No noise.
// ---------------------------------------------------------------------------
__global__ void pilot_kernel(const float* __restrict__ W,
                             const float* __restrict__ b,
                             const float* __restrict__ pm,
                             const int*   __restrict__ pidx,
                             const float* __restrict__ root_pilot)
{
    int t = threadIdx.x;              // sample 0..255
    float x[N_NODES];                 // per-thread (local mem ok, tiny kernel)
    for (int i = 0; i < N_NODES; i++) {
        float m0 = pm[i * 2 + 0], m1 = pm[i * 2 + 1];
        float v;
        if (m0 == 0.f && m1 == 0.f) {
            v = root_pilot[i * CAL_N + t];
        } else {
            int   p0 = pidx[i * 2 + 0], p1 = pidx[i * 2 + 1];
            float w0 = W[i * 2 + 0] * m0, w1 = W[i * 2 + 1] * m1;
            v = fmaxf(fmaf(w0, x[p0], fmaf(w1, x[p1], b[i])), 0.f);
        }
        x[i] = v;
        g_pilot[i * CAL_N + t] = v;
    }
}

// ---------------------------------------------------------------------------
// K2: per-node sigma via exact order statistics (stable rank counting),
// plus per-node constant baking. 128 blocks x 256 threads.
// jnp.quantile linear: q25 at 63.75 -> v[63]+0.75*(v[64]-v[63]),
//                      q75 at 191.25 -> v[191]+0.25*(v[192]-v[191]).
// ---------------------------------------------------------------------------
__global__ void sigma_kernel(const float* __restrict__ W,
                             const float* __restrict__ b,
                             const float* __restrict__ pm,
                             const int*   __restrict__ pidx)
{
    __shared__ float v[CAL_N];
    __shared__ float q[4];
    int node = blockIdx.x;
    int t = threadIdx.x;
    float my = g_pilot[node * CAL_N + t];
    v[t] = my;
    __syncthreads();

    int rank = 0;
    #pragma unroll 8
    for (int j = 0; j < CAL_N; j++) {
        float o = v[j];                            // broadcast read
        rank += (o < my) || (o == my && j < t);    // stable rank: bijection 0..255
    }
    if (rank == 63)  q[0] = my;
    if (rank == 64)  q[1] = my;
    if (rank == 191) q[2] = my;
    if (rank == 192) q[3] = my;
    __syncthreads();

    if (t == 0) {
        float q25 = q[0] + 0.75f * (q[1] - q[0]);
        float q75 = q[2] + 0.25f * (q[3] - q[2]);
        float sig = 0.1f * fmaxf(q75 - q25, 1e-6f);

        float m0 = pm[node * 2 + 0], m1 = pm[node * 2 + 1];
        bool  root = (m0 == 0.f) && (m1 == 0.f);
        int   p0 = pidx[node * 2 + 0] & 0xff;
        int   p1 = pidx[node * 2 + 1] & 0xff;
        if (root) {
            g_cA[node] = make_float4(0.f, 0.f, 0.f, 1.f);
            g_cP[node] = 0x10000;      // p0=p1=0, root flag
        } else {
            g_cA[node] = make_float4(W[node * 2 + 0] * m0,
                                     W[node * 2 + 1] * m1,
                                     b[node], sig);
            g_cP[node] = p0 | (p1 << 8);
        }
    }
}

// ---------------------------------------------------------------------------
// K3: main pass. Each thread owns one sample; node values live in shared
// memory [node][tid] (conflict-free, per-thread-private columns -> no syncs
// inside the loop). Unified formula:
//   v = relu(w0*pv0 + w1*pv1 + b) + scale * LDG((root? root_main : z)[i*n+s])
// Root nodes have w=b=0 (relu of garbage*0 is 0 via fmaxf NaN semantics) and
// scale=1 -> v = root_main value exactly.
// ---------------------------------------------------------------------------
__global__ void __launch_bounds__(SPB)
main_kernel(const float* __restrict__ rm,
            const float* __restrict__ zn,
            const int*   __restrict__ chosen,
            float*       __restrict__ out,
            int n)
{
    extern __shared__ float shv[];         // [N_NODES][SPB] = 64 KB
    __shared__ float4 cA[N_NODES];
    __shared__ int    cP[N_NODES];
    __shared__ int    ch[N_OBS];

    int t = threadIdx.x;
    cA[t] = g_cA[t];
    cP[t] = g_cP[t];
    if (t < N_OBS) ch[t] = chosen[t];
    __syncthreads();

    int s = blockIdx.x * SPB + t;
    if (s < n) {
        const float* pz = zn + s;
        const float* pr = rm + s;
        int off = 0;                       // i*n, max 127*262144 < 2^31

        #pragma unroll 4
        for (int i = 0; i < N_NODES; i++) {
            float4 c  = cA[i];             // uniform LDS.128 broadcast
            int    pk = cP[i];
            float pv0 = shv[(pk & 0xff) * SPB + t];
            float pv1 = shv[((pk >> 8) & 0xff) * SPB + t];
            const float* base = (pk & 0x10000) ? pr : pz;
            float nz = __ldg(base + off);
            float h  = fmaxf(fmaf(c.x, pv0, fmaf(c.y, pv1, c.z)), 0.f);
            shv[i * SPB + t] = fmaf(c.w, nz, h);
            off += n;
        }

        // Gather chosen nodes, write transposed output row [s][0..63] as float4s
        float4* out4 = reinterpret_cast<float4*>(out + (size_t)s * N_OBS);
        #pragma unroll
        for (int j = 0; j < N_OBS / 4; j++) {
            int c0 = ch[4 * j + 0], c1 = ch[4 * j + 1];
            int c2 = ch[4 * j + 2], c3 = ch[4 * j + 3];
            out4[j] = make_float4(shv[c0 * SPB + t], shv[c1 * SPB + t],
                                  shv[c2 * SPB + t], shv[c3 * SPB + t]);
        }
    }
}

// ---------------------------------------------------------------------------
// Launch. Input order per setup_inputs dict:
// 0:n_samples 1:W 2:b 3:root_pilot 4:root_main 5:z_noise
// 6:par_mask 7:par_idx 8:is_root 9:chosen
// (n_samples and is_root are never dereferenced: n from in_sizes, root from mask)
// ---------------------------------------------------------------------------
extern "C" void kernel_launch(void* const* d_in, const int* in_sizes, int n_in,
                              void* d_out, int out_size)
{
    const float* W    = (const float*)d_in[1];
    const float* b    = (const float*)d_in[2];
    const float* rpil = (const float*)d_in[3];
    const float* rm   = (const float*)d_in[4];
    const float* zn   = (const float*)d_in[5];
    const float* pmsk = (const float*)d_in[6];
    const int*   pidx = (const int*)d_in[7];
    const int*   chos = (const int*)d_in[9];
    float*       out  = (float*)d_out;

    int n = in_sizes[4] / N_NODES;     // 262144

    static bool attr_done = false;
    // Setting a func attribute is idempotent and not a captured stream op;
    // do it unconditionally to stay stateless.
    cudaFuncSetAttribute(main_kernel,
                         cudaFuncAttributeMaxDynamicSharedMemorySize,
                         N_NODES * SPB * sizeof(float));
    (void)attr_done;

    pilot_kernel<<<1, CAL_N>>>(W, b, pmsk, pidx, rpil);
    sigma_kernel<<<N_NODES, CAL_N>>>(W, b, pmsk, pidx);

    int grid = (n + SPB - 1) / SPB;    // 2048
    main_kernel<<<grid, SPB, N_NODES * SPB * sizeof(float)>>>(rm, zn, chos, out, n);
}

// round 3
// speedup vs baseline: 3.4019x; 3.4019x over previous
#include <cuda_runtime.h>
#include <cuda_bf16.h>
#include <cstdint>

// Problem constants (fixed by the reference setup)
#define N_NODES   128
#define M_PAR     2
#define CAL_N     256
#define N_OBS     64
#define SPB       128    // samples per block in main kernel
#define PF        16     // noise prefetch depth (register ring)

// Device scratch (allocation-free rule: __device__ globals)
__device__ float  g_pilot[N_NODES * CAL_N];
__device__ float4 g_cA[N_NODES];   // {w0, w1, b, scale}   (root: {0,0,0,1})
__device__ int    g_cP[N_NODES];   // p0 | p1<<8 | root<<16

// ---------------------------------------------------------------------------
// K1: pilot pass. 1 block, 256 threads (one per calibration sample).
// Params preloaded to smem once; node values live in 128KB dynamic smem so
// the per-node chain is LDS-latency (29cyc) not DRAM-latency (600cyc).
// ---------------------------------------------------------------------------
__global__ void __launch_bounds__(CAL_N)
pilot_kernel(const float* __restrict__ W,
             const float* __restrict__ b,
             const float* __restrict__ pm,
             const int*   __restrict__ pidx,
             const float* __restrict__ root_pilot)
{
    extern __shared__ float xs[];          // [N_NODES][CAL_N] = 128 KB
    __shared__ float4 pc[N_NODES];         // {w0, w1, b, rootFlag}
    __shared__ int    pp[N_NODES];

    int t = threadIdx.x;
    if (t < N_NODES) {
        float m0 = pm[t * 2 + 0], m1 = pm[t * 2 + 1];
        bool  root = (m0 == 0.f) && (m1 == 0.f);
        pc[t] = make_float4(W[t * 2 + 0] * m0, W[t * 2 + 1] * m1,
                            b[t], root ? 1.f : 0.f);
        pp[t] = (pidx[t * 2 + 0] & 0xff) | ((pidx[t * 2 + 1] & 0xff) << 8);
    }
    __syncthreads();

    for (int i = 0; i < N_NODES; i++) {
        float4 c  = pc[i];                 // uniform broadcast
        int    pk = pp[i];
        float v;
        if (c.w != 0.f) {                  // root node
            v = root_pilot[i * CAL_N + t];
        } else {
            float pv0 = xs[(pk & 0xff) * CAL_N + t];
            float pv1 = xs[((pk >> 8) & 0xff) * CAL_N + t];
            v = fmaxf(fmaf(c.x, pv0, fmaf(c.y, pv1, c.z)), 0.f);
        }
        xs[i * CAL_N + t] = v;
        g_pilot[i * CAL_N + t] = v;        // coalesced
    }
}

// ---------------------------------------------------------------------------
// K2: per-node sigma via exact order statistics (stable rank counting),
// plus per-node constant baking. 128 blocks x 256 threads.
// jnp.quantile linear: q25 at 63.75 -> v[63]+0.75*(v[64]-v[63]),
//                      q75 at 191.25 -> v[191]+0.25*(v[192]-v[191]).
// ---------------------------------------------------------------------------
__global__ void sigma_kernel(const float* __restrict__ W,
                             const float* __restrict__ b,
                             const float* __restrict__ pm,
                             const int*   __restrict__ pidx)
{
    __shared__ float v[CAL_N];
    __shared__ float q[4];
    int node = blockIdx.x;
    int t = threadIdx.x;
    float my = g_pilot[node * CAL_N + t];
    v[t] = my;
    __syncthreads();

    int rank = 0;
    #pragma unroll 8
    for (int j = 0; j < CAL_N; j++) {
        float o = v[j];                            // broadcast read
        rank += (o < my) || (o == my && j < t);    // stable rank: bijection 0..255
    }
    if (rank == 63)  q[0] = my;
    if (rank == 64)  q[1] = my;
    if (rank == 191) q[2] = my;
    if (rank == 192) q[3] = my;
    __syncthreads();

    if (t == 0) {
        float q25 = q[0] + 0.75f * (q[1] - q[0]);
        float q75 = q[2] + 0.25f * (q[3] - q[2]);
        float sig = 0.1f * fmaxf(q75 - q25, 1e-6f);

        float m0 = pm[node * 2 + 0], m1 = pm[node * 2 + 1];
        bool  root = (m0 == 0.f) && (m1 == 0.f);
        int   p0 = pidx[node * 2 + 0] & 0xff;
        int   p1 = pidx[node * 2 + 1] & 0xff;
        if (root) {
            g_cA[node] = make_float4(0.f, 0.f, 0.f, 1.f);
            g_cP[node] = 0x10000;      // p0=p1=0, root flag
        } else {
            g_cA[node] = make_float4(W[node * 2 + 0] * m0,
                                     W[node * 2 + 1] * m1,
                                     b[node], sig);
            g_cP[node] = p0 | (p1 << 8);
        }
    }
}

// ---------------------------------------------------------------------------
// K3: main pass. One sample per thread; node values in shared [node][tid]
// (conflict-free, thread-private columns -> zero syncs in the loop).
// Noise loads are software-pipelined PF=16 deep through a register ring:
// their addresses depend only on (i, s), so 16 LDGs stay in flight per warp
// (12 warps/SM x 16 x 128B = 24KB outstanding -> DRAM latency fully hidden)
// while the serial LDS->FMA->STS recurrence runs underneath.
//   v_i = relu(w0*pv0 + w1*pv1 + b) + scale * src_i[i*n + s]
// Root nodes: w=b=0, scale=1, src=root_main (fmaxf kills the 0*garbage NaN).
// ---------------------------------------------------------------------------
__global__ void __launch_bounds__(SPB)
main_kernel(const float* __restrict__ rm,
            const float* __restrict__ zn,
            const int*   __restrict__ chosen,
            float*       __restrict__ out,
            int n)
{
    extern __shared__ float shv[];         // [N_NODES][SPB] = 64 KB
    __shared__ float4 cA[N_NODES];
    __shared__ int    cP[N_NODES];
    __shared__ int    ch[N_OBS];

    int t = threadIdx.x;
    cA[t] = g_cA[t];
    cP[t] = g_cP[t];
    if (t < N_OBS) ch[t] = chosen[t];
    __syncthreads();

    int s = blockIdx.x * SPB + t;
    if (s < n) {
        const float* pz = zn + s;
        const float* pr = rm + s;

        // Prime the prefetch ring
        float nz[PF];
        #pragma unroll
        for (int j = 0; j < PF; j++) {
            const float* bp = (cP[j] & 0x10000) ? pr : pz;
            nz[j] = __ldg(bp + j * n);
        }

        #pragma unroll 16
        for (int i = 0; i < N_NODES; i++) {
            float cur = nz[i & (PF - 1)];
            int   ip  = i + PF;
            if (ip < N_NODES) {
                const float* bp = (cP[ip] & 0x10000) ? pr : pz;
                nz[i & (PF - 1)] = __ldg(bp + ip * n);
            }
            float4 c  = cA[i];             // uniform LDS.128 broadcast
            int    pk = cP[i];
            float pv0 = shv[(pk & 0xff) * SPB + t];
            float pv1 = shv[((pk >> 8) & 0xff) * SPB + t];
            float h   = fmaxf(fmaf(c.x, pv0, fmaf(c.y, pv1, c.z)), 0.f);
            shv[i * SPB + t] = fmaf(c.w, cur, h);
        }

        // Gather chosen nodes, write transposed output row [s][0..63] as float4s
        float4* out4 = reinterpret_cast<float4*>(out + (size_t)s * N_OBS);
        #pragma unroll
        for (int j = 0; j < N_OBS / 4; j++) {
            int c0 = ch[4 * j + 0], c1 = ch[4 * j + 1];
            int c2 = ch[4 * j + 2], c3 = ch[4 * j + 3];
            out4[j] = make_float4(shv[c0 * SPB + t], shv[c1 * SPB + t],
                                  shv[c2 * SPB + t], shv[c3 * SPB + t]);
        }
    }
}

// ---------------------------------------------------------------------------
// Launch. Input order per setup_inputs dict:
// 0:n_samples 1:W 2:b 3:root_pilot 4:root_main 5:z_noise
// 6:par_mask 7:par_idx 8:is_root 9:chosen
// ---------------------------------------------------------------------------
extern "C" void kernel_launch(void* const* d_in, const int* in_sizes, int n_in,
                              void* d_out, int out_size)
{
    const float* W    = (const float*)d_in[1];
    const float* b    = (const float*)d_in[2];
    const float* rpil = (const float*)d_in[3];
    const float* rm   = (const float*)d_in[4];
    const float* zn   = (const float*)d_in[5];
    const float* pmsk = (const float*)d_in[6];
    const int*   pidx = (const int*)d_in[7];
    const int*   chos = (const int*)d_in[9];
    float*       out  = (float*)d_out;

    int n = in_sizes[4] / N_NODES;     // 262144

    cudaFuncSetAttribute(pilot_kernel,
                         cudaFuncAttributeMaxDynamicSharedMemorySize,
                         N_NODES * CAL_N * sizeof(float));
    cudaFuncSetAttribute(main_kernel,
                         cudaFuncAttributeMaxDynamicSharedMemorySize,
                         N_NODES * SPB * sizeof(float));

    pilot_kernel<<<1, CAL_N, N_NODES * CAL_N * sizeof(float)>>>(W, b, pmsk, pidx, rpil);
    sigma_kernel<<<N_NODES, CAL_N>>>(W, b, pmsk, pidx);

    int grid = (n + SPB - 1) / SPB;    // 2048
    main_kernel<<<grid, SPB, N_NODES * SPB * sizeof(float)>>>(rm, zn, chos, out, n);
}